// round 5
// baseline (speedup 1.0000x reference)
#include <cuda_runtime.h>

// Fixed problem shapes
#define BB 64
#define CC 64   // C == Co
#define TT 32
#define NN 64
#define KK 3

#define STRIDE 68               // 64 + 4 pad: float4-aligned, bank-spread rows
#define BUF (64 * STRIDE)
#define SMEM_FLOATS (2 * BUF + 3 * 64)
#define SMEM_BYTES  (SMEM_FLOATS * 4)     // 35,584 B -> 5 CTAs/SM

// W transposed once into device-global scratch (WT[c][o] = W[o][c])
__device__ float g_WT[CC * CC];

__global__ void wt_transpose_kernel(const float* __restrict__ W)
{
    const int i = blockIdx.x * 256 + threadIdx.x;   // 0..4095
    const int o = i >> 6;
    const int c = i & 63;
    g_WT[c * CC + o] = W[i];
}

// One CTA per (b, t). 256 threads, 4x4 register tiles, 2 aliased smem buffers.
// Phase order: [A copy (streaming) + stage x/WT] -> GEMM1 -> A-phase (L2 hits)
//              -> GEMM2. Copy-first keeps HBM busy under GEMM1.
__global__ void __launch_bounds__(256, 5)
ctg_kernel(const float* __restrict__ x,
           const float* __restrict__ A,
           const float* __restrict__ bias,
           float* __restrict__ out,
           int copyA)
{
    extern __shared__ float sm[];
    float* s0 = sm;           // x tile -> Asum
    float* s1 = sm + BUF;     // WT -> yT
    float* sD = sm + 2 * BUF; // dinv, 3 slabs of 64

    const int tid = threadIdx.x;
    const int b   = blockIdx.x / TT;
    const int t   = blockIdx.x % TT;
    const int tx  = tid & 15;   // 4-col group
    const int ty  = tid >> 4;   // 4-row group

    const size_t abase = (((size_t)b * KK) * TT + t) * (size_t)(NN * NN); // k=0
    const size_t kstep = (size_t)TT * NN * NN;                            // k stride
    float* outA = out + (size_t)BB * CC * TT * NN;

    // ---- A pass-through copy, front-loaded (streaming hints) ----
    if (copyA) {
        #pragma unroll
        for (int k = 0; k < KK; k++) {
            #pragma unroll
            for (int it = 0; it < 4; it++) {
                const size_t off = abase + k * kstep + ((size_t)(it * 256 + tid)) * 4;
                const float4 v = __ldcg((const float4*)(A + off));
                __stcs((float4*)(outA + off), v);
            }
        }
    }

    // ---- stage x[b,:,t,:] ([c][n]) and WT ([c][o]) via float4 ----
    #pragma unroll
    for (int it = 0; it < 4; it++) {
        const int e4 = it * 256 + tid;    // float4 slot 0..1023
        const int r  = e4 >> 4;
        const int c4 = e4 & 15;
        *(float4*)(s0 + r * STRIDE + c4 * 4) =
            *(const float4*)(x + (((size_t)(b * CC + r) * TT + t) * NN) + c4 * 4);
        *(float4*)(s1 + r * STRIDE + c4 * 4) =
            *(const float4*)(g_WT + (size_t)e4 * 4);
    }
    __syncthreads();

    // ---- GEMM1: yT[n][o] = sum_c x[c][n] * WT[c][o] + bias[o] ----
    float acc[4][4];
    #pragma unroll
    for (int i = 0; i < 4; i++)
        #pragma unroll
        for (int j = 0; j < 4; j++) acc[i][j] = 0.0f;

    #pragma unroll 8
    for (int kk = 0; kk < 64; kk++) {
        const float2 a01 = *(const float2*)(s0 + kk * STRIDE + ty * 4);     // x[kk][4ty..] lo
        const float2 a23 = *(const float2*)(s0 + kk * STRIDE + ty * 4 + 2); // hi
        const float2 b01 = *(const float2*)(s1 + kk * STRIDE + tx * 4);     // WT[kk][4tx..] lo
        const float2 b23 = *(const float2*)(s1 + kk * STRIDE + tx * 4 + 2); // hi
        const float av[4] = {a01.x, a01.y, a23.x, a23.y};
        const float bv[4] = {b01.x, b01.y, b23.x, b23.y};
        #pragma unroll
        for (int i = 0; i < 4; i++) {
            acc[i][0] += av[i] * bv[0];
            acc[i][1] += av[i] * bv[1];
            acc[i][2] += av[i] * bv[2];
            acc[i][3] += av[i] * bv[3];
        }
    }
    __syncthreads();   // all x/WT reads done before overwriting s1 with yT

    {
        const float4 bia = *(const float4*)(bias + tx * 4);
        #pragma unroll
        for (int i = 0; i < 4; i++) {
            float4 r4;
            r4.x = acc[i][0] + bia.x;
            r4.y = acc[i][1] + bia.y;
            r4.z = acc[i][2] + bia.z;
            r4.w = acc[i][3] + bia.w;
            *(float4*)(s1 + (4 * ty + i) * STRIDE + tx * 4) = r4;   // yT[n][o]
        }
    }

    // ---- A-phase: register A_k (L2 hits after the copy) + register Asum ----
    float4 asum[4];
    #pragma unroll
    for (int it = 0; it < 4; it++) { asum[it].x = asum[it].y = asum[it].z = asum[it].w = 0.0f; }

    const int m0 = tx * 4;

    #pragma unroll
    for (int k = 0; k < KK; k++) {
        const size_t base = abase + k * kstep;
        float* sDk = sD + k * 64;

        float4 a[4];
        #pragma unroll
        for (int it = 0; it < 4; it++)
            a[it] = __ldcg((const float4*)(A + base + ((size_t)(it * 256 + tid)) * 4));

        // row degrees: each half-warp holds one full row per it (row = it*16 + ty)
        #pragma unroll
        for (int it = 0; it < 4; it++) {
            float s = a[it].x + a[it].y + a[it].z + a[it].w;
            s += __shfl_xor_sync(0xffffffffu, s, 1);
            s += __shfl_xor_sync(0xffffffffu, s, 2);
            s += __shfl_xor_sync(0xffffffffu, s, 4);
            s += __shfl_xor_sync(0xffffffffu, s, 8);
            if (tx == 0) sDk[it * 16 + ty] = rsqrtf(s + 1.0f);   // A_tilde = A + I
        }
        __syncthreads();

        const float4 dm = *(const float4*)(sDk + m0);
        #pragma unroll
        for (int it = 0; it < 4; it++) {
            const int n = it * 16 + ty;
            const float dn = sDk[n];
            float4 v = a[it];
            const int d = n - m0;
            if (d == 0) v.x += 1.0f;
            if (d == 1) v.y += 1.0f;
            if (d == 2) v.z += 1.0f;
            if (d == 3) v.w += 1.0f;
            asum[it].x += v.x * dn * dm.x;
            asum[it].y += v.y * dn * dm.y;
            asum[it].z += v.z * dn * dm.z;
            asum[it].w += v.w * dn * dm.w;
        }
        // no trailing sync: next k writes a different sD slab
    }

    // Asum -> s0 (x is dead since post-GEMM1 barrier)
    #pragma unroll
    for (int it = 0; it < 4; it++)
        *(float4*)(s0 + (it * 16 + ty) * STRIDE + m0) = asum[it];
    __syncthreads();

    // ---- GEMM2: x_out[c][m] = sum_n yT[n][c] * Asum[n][m] ----
    #pragma unroll
    for (int i = 0; i < 4; i++)
        #pragma unroll
        for (int j = 0; j < 4; j++) acc[i][j] = 0.0f;

    #pragma unroll 8
    for (int kk = 0; kk < 64; kk++) {
        const float2 a01 = *(const float2*)(s1 + kk * STRIDE + ty * 4);     // yT[kk][4ty..]
        const float2 a23 = *(const float2*)(s1 + kk * STRIDE + ty * 4 + 2);
        const float2 b01 = *(const float2*)(s0 + kk * STRIDE + tx * 4);     // Asum[kk][4tx..]
        const float2 b23 = *(const float2*)(s0 + kk * STRIDE + tx * 4 + 2);
        const float av[4] = {a01.x, a01.y, a23.x, a23.y};
        const float bv[4] = {b01.x, b01.y, b23.x, b23.y};
        #pragma unroll
        for (int i = 0; i < 4; i++) {
            acc[i][0] += av[i] * bv[0];
            acc[i][1] += av[i] * bv[1];
            acc[i][2] += av[i] * bv[2];
            acc[i][3] += av[i] * bv[3];
        }
    }

    #pragma unroll
    for (int i = 0; i < 4; i++) {
        const int c = 4 * ty + i;
        float4 r4;
        r4.x = acc[i][0]; r4.y = acc[i][1]; r4.z = acc[i][2]; r4.w = acc[i][3];
        *(float4*)(out + (((size_t)(b * CC + c) * TT + t) * NN) + m0) = r4;
    }
}

extern "C" void kernel_launch(void* const* d_in, const int* in_sizes, int n_in,
                              void* d_out, int out_size)
{
    const float* x    = (const float*)d_in[0];
    const float* A    = (const float*)d_in[1];
    const float* W    = (const float*)d_in[2];
    const float* bias = (const float*)d_in[3];
    float* out = (float*)d_out;

    const int xout_elems = BB * CC * TT * NN;           // 8,388,608
    const int copyA = (out_size > xout_elems) ? 1 : 0;  // tuple output (x_out, A)

    wt_transpose_kernel<<<16, 256>>>(W);

    cudaFuncSetAttribute(ctg_kernel, cudaFuncAttributeMaxDynamicSharedMemorySize, SMEM_BYTES);
    ctg_kernel<<<BB * TT, 256, SMEM_BYTES>>>(x, A, bias, out, copyA);
}

// round 6
// speedup vs baseline: 1.2437x; 1.2437x over previous
#include <cuda_runtime.h>

// Fixed problem shapes
#define BB 64
#define CC 64   // C == Co
#define TT 32
#define NN 64
#define KK 3

#define STRIDE 68               // 64 + 4 pad: float4-aligned, bank-spread rows
#define BUF (64 * STRIDE)
#define SMEM_FLOATS (2 * BUF + 3 * 64)
#define SMEM_BYTES  (SMEM_FLOATS * 4)     // 35,584 B -> 5 CTAs/SM

// W transposed once into device-global scratch (WT[c][o] = W[o][c])
__device__ float g_WT[CC * CC];

__global__ void wt_transpose_kernel(const float* __restrict__ W)
{
    const int i = blockIdx.x * 256 + threadIdx.x;   // 0..4095
    const int o = i >> 6;
    const int c = i & 63;
    g_WT[c * CC + o] = W[i];
}

// Forced 64-bit shared loads (ptxas must not re-fuse into LDS.128)
#define LDS64(v0, v1, addr) \
    asm("ld.shared.v2.f32 {%0,%1}, [%2];" : "=f"(v0), "=f"(v1) : "r"(addr))

// One CTA per (b, t). 256 threads, 4x4 register tiles, 2 aliased smem buffers.
// s0: x tile [c][n]  -> Asum [n][m]
// s1: WT tile [c][o] -> yT tile [n][o]
// sD: dinv, 3 slabs of 64 (one per k -> no trailing barrier per k)
__global__ void __launch_bounds__(256, 5)
ctg_kernel(const float* __restrict__ x,
           const float* __restrict__ A,
           const float* __restrict__ bias,
           float* __restrict__ out,
           int copyA)
{
    extern __shared__ float sm[];
    float* s0 = sm;
    float* s1 = sm + BUF;
    float* sD = sm + 2 * BUF;

    const unsigned s0b = (unsigned)__cvta_generic_to_shared(s0);
    const unsigned s1b = (unsigned)__cvta_generic_to_shared(s1);

    const int tid = threadIdx.x;
    const int b   = blockIdx.x / TT;
    const int t   = blockIdx.x % TT;
    const int tx  = tid & 15;   // 4-col group
    const int ty  = tid >> 4;   // 4-row group

    // ---- stage x[b,:,t,:] ([c][n]) and WT ([c][o]) via float4 ----
    #pragma unroll
    for (int it = 0; it < 4; it++) {
        const int e4 = it * 256 + tid;    // float4 slot 0..1023
        const int r  = e4 >> 4;
        const int c4 = e4 & 15;
        *(float4*)(s0 + r * STRIDE + c4 * 4) =
            *(const float4*)(x + (((size_t)(b * CC + r) * TT + t) * NN) + c4 * 4);
        *(float4*)(s1 + r * STRIDE + c4 * 4) =
            *(const float4*)(g_WT + (size_t)e4 * 4);
    }
    __syncthreads();

    // ---- GEMM1: yT[n][o] = sum_c x[c][n] * WT[c][o] + bias[o] ----
    float acc[4][4];
    #pragma unroll
    for (int i = 0; i < 4; i++)
        #pragma unroll
        for (int j = 0; j < 4; j++) acc[i][j] = 0.0f;

    #pragma unroll 8
    for (int kk = 0; kk < 64; kk++) {
        const unsigned aaddr = s0b + (unsigned)(kk * STRIDE + ty * 4) * 4u;
        const unsigned baddr = s1b + (unsigned)(kk * STRIDE + tx * 4) * 4u;
        float a0, a1, a2, a3, b0, b1, b2, b3;
        LDS64(a0, a1, aaddr);        // x[kk][4ty..]   (broadcast, N=1)
        LDS64(a2, a3, aaddr + 8);
        LDS64(b0, b1, baddr);        // WT[kk][4tx..]  (conflict-free 256B)
        LDS64(b2, b3, baddr + 8);
        acc[0][0] += a0 * b0; acc[0][1] += a0 * b1; acc[0][2] += a0 * b2; acc[0][3] += a0 * b3;
        acc[1][0] += a1 * b0; acc[1][1] += a1 * b1; acc[1][2] += a1 * b2; acc[1][3] += a1 * b3;
        acc[2][0] += a2 * b0; acc[2][1] += a2 * b1; acc[2][2] += a2 * b2; acc[2][3] += a2 * b3;
        acc[3][0] += a3 * b0; acc[3][1] += a3 * b1; acc[3][2] += a3 * b2; acc[3][3] += a3 * b3;
    }
    __syncthreads();   // all x/WT reads done before overwriting s1 with yT

    {
        const float4 bia = *(const float4*)(bias + tx * 4);
        #pragma unroll
        for (int i = 0; i < 4; i++) {
            float4 r4;
            r4.x = acc[i][0] + bia.x;
            r4.y = acc[i][1] + bia.y;
            r4.z = acc[i][2] + bia.z;
            r4.w = acc[i][3] + bia.w;
            *(float4*)(s1 + (4 * ty + i) * STRIDE + tx * 4) = r4;   // yT[n][o]
        }
    }

    // ---- A-phase: register A_k + register Asum, shfl row degrees ----
    float* outA = out + (size_t)BB * CC * TT * NN;

    float4 asum[4];
    #pragma unroll
    for (int it = 0; it < 4; it++) { asum[it].x = asum[it].y = asum[it].z = asum[it].w = 0.0f; }

    const int m0 = tx * 4;

    #pragma unroll
    for (int k = 0; k < KK; k++) {
        const size_t base = (((size_t)b * KK + k) * TT + t) * (size_t)(NN * NN);
        float* sDk = sD + k * 64;

        float4 a[4];
        #pragma unroll
        for (int it = 0; it < 4; it++) {
            const int e4 = it * 256 + tid;
            a[it] = *(const float4*)(A + base + (size_t)e4 * 4);
            if (copyA) *(float4*)(outA + base + (size_t)e4 * 4) = a[it];
        }

        // row degrees: each half-warp holds one full row per it (row = it*16 + ty)
        #pragma unroll
        for (int it = 0; it < 4; it++) {
            float s = a[it].x + a[it].y + a[it].z + a[it].w;
            s += __shfl_xor_sync(0xffffffffu, s, 1);
            s += __shfl_xor_sync(0xffffffffu, s, 2);
            s += __shfl_xor_sync(0xffffffffu, s, 4);
            s += __shfl_xor_sync(0xffffffffu, s, 8);
            if (tx == 0) sDk[it * 16 + ty] = rsqrtf(s + 1.0f);   // A_tilde = A + I
        }
        __syncthreads();

        const float4 dm = *(const float4*)(sDk + m0);
        #pragma unroll
        for (int it = 0; it < 4; it++) {
            const int n = it * 16 + ty;
            const float dn = sDk[n];
            float4 v = a[it];
            const int d = n - m0;
            if (d == 0) v.x += 1.0f;
            if (d == 1) v.y += 1.0f;
            if (d == 2) v.z += 1.0f;
            if (d == 3) v.w += 1.0f;
            asum[it].x += v.x * dn * dm.x;
            asum[it].y += v.y * dn * dm.y;
            asum[it].z += v.z * dn * dm.z;
            asum[it].w += v.w * dn * dm.w;
        }
        // no trailing sync: next k writes a different sD slab
    }

    // Asum -> s0 (x is dead since post-GEMM1 barrier)
    #pragma unroll
    for (int it = 0; it < 4; it++)
        *(float4*)(s0 + (it * 16 + ty) * STRIDE + m0) = asum[it];
    __syncthreads();

    // ---- GEMM2: x_out[c][m] = sum_n yT[n][c] * Asum[n][m] ----
    #pragma unroll
    for (int i = 0; i < 4; i++)
        #pragma unroll
        for (int j = 0; j < 4; j++) acc[i][j] = 0.0f;

    #pragma unroll 8
    for (int kk = 0; kk < 64; kk++) {
        const unsigned aaddr = s1b + (unsigned)(kk * STRIDE + ty * 4) * 4u;
        const unsigned baddr = s0b + (unsigned)(kk * STRIDE + tx * 4) * 4u;
        float a0, a1, a2, a3, b0, b1, b2, b3;
        LDS64(a0, a1, aaddr);        // yT[kk][4ty..]   (broadcast)
        LDS64(a2, a3, aaddr + 8);
        LDS64(b0, b1, baddr);        // Asum[kk][4tx..] (conflict-free)
        LDS64(b2, b3, baddr + 8);
        acc[0][0] += a0 * b0; acc[0][1] += a0 * b1; acc[0][2] += a0 * b2; acc[0][3] += a0 * b3;
        acc[1][0] += a1 * b0; acc[1][1] += a1 * b1; acc[1][2] += a1 * b2; acc[1][3] += a1 * b3;
        acc[2][0] += a2 * b0; acc[2][1] += a2 * b1; acc[2][2] += a2 * b2; acc[2][3] += a2 * b3;
        acc[3][0] += a3 * b0; acc[3][1] += a3 * b1; acc[3][2] += a3 * b2; acc[3][3] += a3 * b3;
    }

    #pragma unroll
    for (int i = 0; i < 4; i++) {
        const int c = 4 * ty + i;
        float4 r4;
        r4.x = acc[i][0]; r4.y = acc[i][1]; r4.z = acc[i][2]; r4.w = acc[i][3];
        *(float4*)(out + (((size_t)(b * CC + c) * TT + t) * NN) + m0) = r4;
    }
}

extern "C" void kernel_launch(void* const* d_in, const int* in_sizes, int n_in,
                              void* d_out, int out_size)
{
    const float* x    = (const float*)d_in[0];
    const float* A    = (const float*)d_in[1];
    const float* W    = (const float*)d_in[2];
    const float* bias = (const float*)d_in[3];
    float* out = (float*)d_out;

    const int xout_elems = BB * CC * TT * NN;           // 8,388,608
    const int copyA = (out_size > xout_elems) ? 1 : 0;  // tuple output (x_out, A)

    wt_transpose_kernel<<<16, 256>>>(W);

    cudaFuncSetAttribute(ctg_kernel, cudaFuncAttributeMaxDynamicSharedMemorySize, SMEM_BYTES);
    ctg_kernel<<<BB * TT, 256, SMEM_BYTES>>>(x, A, bias, out, copyA);
}